// round 3
// baseline (speedup 1.0000x reference)
#include <cuda_runtime.h>
#include <cstdint>
#include <math.h>

#define BB 64
#define TT 1380
#define XD 96
#define HD 192
#define CN 345

// ---------------- scratch ----------------
static __device__ float g_M1[(size_t)BB * CN * XD];   // W2 @ X[b]
static __device__ float g_G [(size_t)BB * CN * HD];   // (M1 @ W1)*SCALE
static __device__ float g_S [(size_t)BB * CN * TT];   // logits
static __device__ float g_rmax[BB * CN];
static __device__ float g_rinv[BB * CN];

// ---------------- tf32 split helpers ----------------
__device__ __forceinline__ uint32_t to_tf32(float x) {
    uint32_t r;
    asm("cvt.rna.tf32.f32 %0, %1;" : "=r"(r) : "f"(x));
    return r;
}
__device__ __forceinline__ void split_tf32(float x, float& hi, float& lo) {
    uint32_t h = to_tf32(x);
    hi = __uint_as_float(h);
    lo = __uint_as_float(to_tf32(x - hi));
}

// mma.sync m16n8k8 tf32 (row.col), D += A*B
__device__ __forceinline__ void mma8(float* d, const uint32_t* a, const uint32_t* b) {
    asm volatile(
        "mma.sync.aligned.m16n8k8.row.col.f32.tf32.tf32.f32 "
        "{%0,%1,%2,%3}, {%4,%5,%6,%7}, {%8,%9}, {%0,%1,%2,%3};"
        : "+f"(d[0]), "+f"(d[1]), "+f"(d[2]), "+f"(d[3])
        : "r"(a[0]), "r"(a[1]), "r"(a[2]), "r"(a[3]), "r"(b[0]), "r"(b[1]));
}

// ---------------------------------------------------------------------------
// tf32-split tensor-core GEMM.
//   C[b][m][n] = alpha * sum_k A[b][m][k] * Bop[k][n]
//   BTRANS=0: Bop[k][n] = Bsrc[n*ldb + k]   (B rows are n, e.g. A @ H^T)
//   BTRANS=1: Bop[k][n] = Bsrc[k*ldb + n]   (B rows are k, e.g. A @ W)
//   ASOFT=1 : A entries transformed exp(a - rmax[m]) * rinv[m] on load.
// CTA tile 128x128x16, 256 threads, warps 2(m) x 4(n), warp tile 64x32.
// ---------------------------------------------------------------------------
#define SA 20   // smem row stride (floats): conflict-free for quad pattern

template <int BTRANS, int ASOFT>
__global__ void __launch_bounds__(256) gemm_mma(
    const float* __restrict__ A, const float* __restrict__ Bsrc, float* __restrict__ C,
    int M, int N, int K, int lda, int ldb, int ldc,
    long sA, long sB, long sC, float alpha,
    const float* __restrict__ rmaxA, const float* __restrict__ rinvA, int statStride)
{
    __shared__ float As_hi[128][SA], As_lo[128][SA];
    __shared__ float Bs_hi[128][SA], Bs_lo[128][SA];

    const int tid  = threadIdx.x;
    const int wid  = tid >> 5, lane = tid & 31;
    const int wm   = wid >> 2, wn = wid & 3;      // 2 x 4 warp grid
    const int grp  = lane >> 2, qid = lane & 3;   // quad decomposition
    const int b    = blockIdx.z;

    A    += (long)b * sA;
    Bsrc += (long)b * sB;
    C    += (long)b * sC;
    const float* rmax = rmaxA + (long)b * statStride;
    const float* rinv = rinvA + (long)b * statStride;

    const int m0 = blockIdx.y * 128;
    const int n0 = blockIdx.x * 128;

    float acc[4][4][4];
#pragma unroll
    for (int i = 0; i < 4; i++)
#pragma unroll
        for (int j = 0; j < 4; j++)
#pragma unroll
            for (int r = 0; r < 4; r++) acc[i][j][r] = 0.f;

    const int nb = (K + 15) >> 4;
    float4 pa[2], pb[2];

    // ---- prefetch helpers (inlined per iteration) ----
    auto loadA = [&](int kb) {
#pragma unroll
        for (int i = 0; i < 2; i++) {
            const int f = tid + i * 256;
            const int row = f >> 2, c4 = f & 3;
            const int gm = m0 + row, gk = (kb << 4) + c4 * 4;
            float4 v = make_float4(0.f, 0.f, 0.f, 0.f);
            if (gm < M && gk + 4 <= K)
                v = *reinterpret_cast<const float4*>(A + (long)gm * lda + gk);
            pa[i] = v;
        }
    };
    auto storeA = [&]() {
#pragma unroll
        for (int i = 0; i < 2; i++) {
            const int f = tid + i * 256;
            const int row = f >> 2, c4 = f & 3;
            float4 v = pa[i];
            if (ASOFT) {
                const int gm = m0 + row;
                const float mx = (gm < M) ? rmax[gm] : 0.f;
                const float rv = (gm < M) ? rinv[gm] : 0.f;
                v.x = __expf(v.x - mx) * rv;
                v.y = __expf(v.y - mx) * rv;
                v.z = __expf(v.z - mx) * rv;
                v.w = __expf(v.w - mx) * rv;
                if (gm >= M) { v.x = v.y = v.z = v.w = 0.f; }
            }
            float h, l;
            split_tf32(v.x, h, l); As_hi[row][c4*4+0] = h; As_lo[row][c4*4+0] = l;
            split_tf32(v.y, h, l); As_hi[row][c4*4+1] = h; As_lo[row][c4*4+1] = l;
            split_tf32(v.z, h, l); As_hi[row][c4*4+2] = h; As_lo[row][c4*4+2] = l;
            split_tf32(v.w, h, l); As_hi[row][c4*4+3] = h; As_lo[row][c4*4+3] = l;
        }
    };
    auto loadB = [&](int kb) {
        if (BTRANS == 0) {
#pragma unroll
            for (int i = 0; i < 2; i++) {
                const int f = tid + i * 256;
                const int row = f >> 2, c4 = f & 3;
                const int gn = n0 + row, gk = (kb << 4) + c4 * 4;
                float4 v = make_float4(0.f, 0.f, 0.f, 0.f);
                if (gn < N && gk + 4 <= K)
                    v = *reinterpret_cast<const float4*>(Bsrc + (long)gn * ldb + gk);
                pb[i] = v;
            }
        } else {
#pragma unroll
            for (int i = 0; i < 2; i++) {
                const int f = tid + i * 256;
                const int kc = f >> 5, n4 = f & 31;
                const int gk = (kb << 4) + kc, gn = n0 + n4 * 4;
                float4 v = make_float4(0.f, 0.f, 0.f, 0.f);
                if (gk < K && gn + 4 <= N)
                    v = *reinterpret_cast<const float4*>(Bsrc + (long)gk * ldb + gn);
                pb[i] = v;
            }
        }
    };
    auto storeB = [&]() {
        if (BTRANS == 0) {
#pragma unroll
            for (int i = 0; i < 2; i++) {
                const int f = tid + i * 256;
                const int row = f >> 2, c4 = f & 3;
                const float4 v = pb[i];
                float h, l;
                split_tf32(v.x, h, l); Bs_hi[row][c4*4+0] = h; Bs_lo[row][c4*4+0] = l;
                split_tf32(v.y, h, l); Bs_hi[row][c4*4+1] = h; Bs_lo[row][c4*4+1] = l;
                split_tf32(v.z, h, l); Bs_hi[row][c4*4+2] = h; Bs_lo[row][c4*4+2] = l;
                split_tf32(v.w, h, l); Bs_hi[row][c4*4+3] = h; Bs_lo[row][c4*4+3] = l;
            }
        } else {
#pragma unroll
            for (int i = 0; i < 2; i++) {
                const int f = tid + i * 256;
                const int kc = f >> 5, n4 = f & 31;
                const float4 v = pb[i];
                float h, l;
                split_tf32(v.x, h, l); Bs_hi[n4*4+0][kc] = h; Bs_lo[n4*4+0][kc] = l;
                split_tf32(v.y, h, l); Bs_hi[n4*4+1][kc] = h; Bs_lo[n4*4+1][kc] = l;
                split_tf32(v.z, h, l); Bs_hi[n4*4+2][kc] = h; Bs_lo[n4*4+2][kc] = l;
                split_tf32(v.w, h, l); Bs_hi[n4*4+3][kc] = h; Bs_lo[n4*4+3][kc] = l;
            }
        }
    };

    // ---- pipeline ----
    loadA(0); loadB(0);
    storeA(); storeB();
    __syncthreads();

    for (int kb = 0; kb < nb; kb++) {
        const bool more = (kb + 1 < nb);
        if (more) { loadA(kb + 1); loadB(kb + 1); }

        // ---- compute this tile ----
#pragma unroll
        for (int k8 = 0; k8 < 2; k8++) {
            const int kk = k8 * 8;
            uint32_t Ah[4][4], Al[4][4], Bh[4][2], Bl[4][2];
#pragma unroll
            for (int mt = 0; mt < 4; mt++) {
                const int r0 = wm * 64 + mt * 16 + grp;
                Ah[mt][0] = __float_as_uint(As_hi[r0    ][kk + qid    ]);
                Ah[mt][1] = __float_as_uint(As_hi[r0 + 8][kk + qid    ]);
                Ah[mt][2] = __float_as_uint(As_hi[r0    ][kk + qid + 4]);
                Ah[mt][3] = __float_as_uint(As_hi[r0 + 8][kk + qid + 4]);
                Al[mt][0] = __float_as_uint(As_lo[r0    ][kk + qid    ]);
                Al[mt][1] = __float_as_uint(As_lo[r0 + 8][kk + qid    ]);
                Al[mt][2] = __float_as_uint(As_lo[r0    ][kk + qid + 4]);
                Al[mt][3] = __float_as_uint(As_lo[r0 + 8][kk + qid + 4]);
            }
#pragma unroll
            for (int nt = 0; nt < 4; nt++) {
                const int c0 = wn * 32 + nt * 8 + grp;
                Bh[nt][0] = __float_as_uint(Bs_hi[c0][kk + qid    ]);
                Bh[nt][1] = __float_as_uint(Bs_hi[c0][kk + qid + 4]);
                Bl[nt][0] = __float_as_uint(Bs_lo[c0][kk + qid    ]);
                Bl[nt][1] = __float_as_uint(Bs_lo[c0][kk + qid + 4]);
            }
#pragma unroll
            for (int mt = 0; mt < 4; mt++)
#pragma unroll
                for (int nt = 0; nt < 4; nt++) {
                    mma8(acc[mt][nt], Ah[mt], Bh[nt]);
                    mma8(acc[mt][nt], Ah[mt], Bl[nt]);
                    mma8(acc[mt][nt], Al[mt], Bh[nt]);
                }
        }

        __syncthreads();
        if (more) {
            storeA(); storeB();
            __syncthreads();
        }
    }

    // ---- epilogue ----
#pragma unroll
    for (int mt = 0; mt < 4; mt++) {
#pragma unroll
        for (int nt = 0; nt < 4; nt++) {
            const int gm0 = m0 + wm * 64 + mt * 16 + grp;
            const int gn0 = n0 + wn * 32 + nt * 8 + qid * 2;
            if (gn0 + 2 <= N) {
                if (gm0 < M) {
                    float2 v = make_float2(acc[mt][nt][0] * alpha, acc[mt][nt][1] * alpha);
                    *reinterpret_cast<float2*>(C + (long)gm0 * ldc + gn0) = v;
                }
                if (gm0 + 8 < M) {
                    float2 v = make_float2(acc[mt][nt][2] * alpha, acc[mt][nt][3] * alpha);
                    *reinterpret_cast<float2*>(C + (long)(gm0 + 8) * ldc + gn0) = v;
                }
            }
        }
    }
}

// ---------------------------------------------------------------------------
// Single-pass online softmax stats per row: rmax, 1/sum(exp(x-max))
// ---------------------------------------------------------------------------
__global__ void __launch_bounds__(128) softmax_stats(
    const float* __restrict__ S, float* __restrict__ rmax, float* __restrict__ rinv)
{
    const long row = blockIdx.x;
    const float4* p = reinterpret_cast<const float4*>(S + row * (long)TT);
    const int tid = threadIdx.x;

    float m = -3.0e38f, s = 0.f;
    for (int j = tid; j < TT / 4; j += 128) {
        const float4 v = p[j];
        const float mv = fmaxf(fmaxf(v.x, v.y), fmaxf(v.z, v.w));
        if (mv > m) { s *= __expf(m - mv); m = mv; }
        s += __expf(v.x - m) + __expf(v.y - m) + __expf(v.z - m) + __expf(v.w - m);
    }
#pragma unroll
    for (int o = 16; o; o >>= 1) {
        const float m2 = __shfl_xor_sync(0xffffffffu, m, o);
        const float s2 = __shfl_xor_sync(0xffffffffu, s, o);
        const float M = fmaxf(m, m2);
        s = s * __expf(m - M) + s2 * __expf(m2 - M);
        m = M;
    }
    __shared__ float sm[4], ss[4];
    if ((tid & 31) == 0) { sm[tid >> 5] = m; ss[tid >> 5] = s; }
    __syncthreads();
    if (tid == 0) {
        float M = sm[0];
#pragma unroll
        for (int i = 1; i < 4; i++) M = fmaxf(M, sm[i]);
        float S_ = 0.f;
#pragma unroll
        for (int i = 0; i < 4; i++) S_ += ss[i] * __expf(sm[i] - M);
        rmax[row] = M;
        rinv[row] = 1.0f / S_;
    }
}

// ---------------------------------------------------------------------------
extern "C" void kernel_launch(void* const* d_in, const int* in_sizes, int n_in,
                              void* d_out, int out_size)
{
    const float* X  = (const float*)d_in[0];   // [B,T,XD]
    const float* H  = (const float*)d_in[1];   // [B,T,HD]
    const float* W1 = (const float*)d_in[2];   // [XD,HD]
    const float* W2 = (const float*)d_in[3];   // [CN,T]
    float* out = (float*)d_out;                // [B,CN,HD]

    float *M1, *G, *S, *rmax, *rinv;
    cudaGetSymbolAddress((void**)&M1,   g_M1);
    cudaGetSymbolAddress((void**)&G,    g_G);
    cudaGetSymbolAddress((void**)&S,    g_S);
    cudaGetSymbolAddress((void**)&rmax, g_rmax);
    cudaGetSymbolAddress((void**)&rinv, g_rinv);

    const float SCALE = (float)(1.0 / (sqrt((double)XD) * sqrt((double)HD)));

    // K1: M1[b] = W2 @ X[b]           [CN,XD], K=T.  Bop[k][n]=X[k][n] -> TRANS
    gemm_mma<1,0><<<dim3(1, 3, BB), 256>>>(
        W2, X, M1, CN, XD, TT, TT, XD, XD,
        0L, (long)TT * XD, (long)CN * XD, 1.0f, rmax, rinv, 0);

    // K2: G[b] = (M1[b] @ W1)*SCALE   [CN,HD], K=XD. Bop[k][n]=W1[k][n] -> TRANS
    gemm_mma<1,0><<<dim3(2, 3, BB), 256>>>(
        M1, W1, G, CN, HD, XD, XD, HD, HD,
        (long)CN * XD, 0L, (long)CN * HD, SCALE, rmax, rinv, 0);

    // K3: S[b] = G[b] @ H[b]^T        [CN,T], K=HD.  Bop[k][n]=H[n][k] -> DIRECT
    gemm_mma<0,0><<<dim3(11, 3, BB), 256>>>(
        G, H, S, CN, TT, HD, HD, HD, TT,
        (long)CN * HD, (long)TT * HD, (long)CN * TT, 1.0f, rmax, rinv, 0);

    // K4: online softmax stats
    softmax_stats<<<BB * CN, 128>>>(S, rmax, rinv);

    // K5: out[b] = softmax(S[b]) @ H[b]  [CN,HD], K=T. Bop[k][n]=H[k][n] -> TRANS
    gemm_mma<1,1><<<dim3(2, 3, BB), 256>>>(
        S, H, out, CN, HD, TT, TT, HD, HD,
        (long)CN * TT, (long)TT * HD, (long)CN * HD, 1.0f, rmax, rinv, CN);
}